// round 8
// baseline (speedup 1.0000x reference)
#include <cuda_runtime.h>
#include <cstdint>

#define NSUB 8
#define BTOK 4096
#define DIN  512
#define DFF  2048
#define DOUT 512

// ---- device-global scratch ----
__device__ int   g_tok[BTOK];
__device__ int   g_off[NSUB + 1];
__device__ float g_h[(size_t)BTOK * DFF];   // intermediate h, compact rows

// ===========================================================================
// Routing
// ===========================================================================
__global__ void route_kernel(const int* __restrict__ groups)
{
    __shared__ int s_cnt[NSUB];
    __shared__ int s_cur[NSUB];
    const int tid = threadIdx.x;
    if (tid < NSUB) s_cnt[tid] = 0;
    __syncthreads();
    for (int b = tid; b < BTOK; b += blockDim.x)
        atomicAdd(&s_cnt[groups[2 * b]], 1);
    __syncthreads();
    if (tid == 0) {
        int off = 0;
        for (int e = 0; e < NSUB; ++e) { g_off[e] = off; s_cur[e] = off; off += s_cnt[e]; }
        g_off[NSUB] = off;
    }
    __syncthreads();
    for (int b = tid; b < BTOK; b += blockDim.x) {
        int e = groups[2 * b];
        int pos = atomicAdd(&s_cur[e], 1);
        g_tok[pos] = b;
    }
}

// ===========================================================================
// helpers
// ===========================================================================
__device__ __forceinline__ uint32_t f2tf(float x) {
    uint32_t u;
    asm("cvt.rna.tf32.f32 %0, %1;" : "=r"(u) : "f"(x));
    return u;
}
__device__ __forceinline__ void mma8(float* c, const uint32_t* a, const uint32_t* b) {
    asm volatile(
        "mma.sync.aligned.m16n8k8.row.col.f32.tf32.tf32.f32 "
        "{%0,%1,%2,%3}, {%4,%5,%6,%7}, {%8,%9}, {%0,%1,%2,%3};"
        : "+f"(c[0]), "+f"(c[1]), "+f"(c[2]), "+f"(c[3])
        : "r"(a[0]), "r"(a[1]), "r"(a[2]), "r"(a[3]), "r"(b[0]), "r"(b[1]));
}
__device__ __forceinline__ void cp16(uint32_t dst_smem, const void* src) {
    asm volatile("cp.async.cg.shared.global [%0], [%1], 16;"
                 :: "r"(dst_smem), "l"(src));
}
__device__ __forceinline__ uint32_t smem_u32(const void* p) {
    uint32_t a;
    asm("{ .reg .u64 t; cvta.to.shared.u64 t, %1; cvt.u32.u64 %0, t; }" : "=r"(a) : "l"(p));
    return a;
}

// ===========================================================================
// tf32 mma.sync GEMM: 128x128 tile, BK=16, 3-stage cp.async pipeline.
// Stage (16KB): A [128 rows][16 f] (64B rows, swizzled) | B [16 k][128 f].
// tf32 RNE conversion happens at fragment-read time (identical numerics to
// converting at store). Dynamic smem = 49152B (48KB cap, no FuncSetAttribute).
//   FIRST:  h = relu(x[gather] @ W1[e] + b1)  -> g_h (compact rows)
//   !FIRST: y = h @ W2[e] + b2                -> out (scatter by token)
// ===========================================================================
template <int K, int NTOT, bool FIRST>
__global__ __launch_bounds__(256)
void moe_mma_gemm(const float* __restrict__ X,
                  const float* __restrict__ W,
                  const float* __restrict__ bias,
                  float* __restrict__ Y)
{
    constexpr int KT    = K / 16;
    constexpr int STAGE = 16384;           // 8KB A + 8KB B

    const int e   = blockIdx.z;
    const int off = g_off[e];
    const int cnt = g_off[e + 1] - off;
    const int m0  = blockIdx.y * 128;
    if (m0 >= cnt) return;
    const int n0  = blockIdx.x * 128;

    extern __shared__ char sm[];
    const uint32_t smu = smem_u32(sm);

    const int tid = threadIdx.x;
    const int wid = tid >> 5, l = tid & 31;
    const int g = l >> 2, tig = l & 3;
    const int wm = wid & 3;                // m offset: wm*32
    const int wn = wid >> 2;               // n offset: wn*64

    // ---- cp.async mappings: 4 x 16B per thread per chunk ----
    // A: 512 segs (row = seg>>2, c4 = seg&3); thread t -> segs t, t+256
    const char* aCpPtr[2];
    uint32_t    aCpOff[2];
    #pragma unroll
    for (int j = 0; j < 2; ++j) {
        const int row = (tid >> 2) + 64 * j;
        const int c4  = tid & 3;
        const int r   = m0 + row;
        const int rr  = (r < cnt) ? r : (cnt - 1);
        const float* base;
        if (FIRST) base = X   + (size_t)g_tok[off + rr] * K;
        else       base = g_h + (size_t)(off + rr) * K;
        aCpPtr[j] = (const char*)base + c4 * 16;
        aCpOff[j] = row * 64 + ((c4 ^ ((row >> 1) & 3)) << 4);
    }
    // B: 512 segs (lr = seg>>5, n4 = seg&31); thread t -> segs t, t+256
    const char* bCpPtr[2];
    uint32_t    bCpOff[2];
    #pragma unroll
    for (int j = 0; j < 2; ++j) {
        const int lr = (tid >> 5) + 8 * j;
        const int n4 = tid & 31;
        bCpPtr[j] = (const char*)(W + (size_t)e * K * NTOT + (size_t)lr * NTOT + n0 + n4 * 4);
        bCpOff[j] = 8192 + lr * 512 + ((n4 ^ ((lr & 3) << 1)) << 4);
    }

    // ---- fragment-read bases (conflict-free, enumerated) ----
    uint32_t rowb[4], uxr[4];
    #pragma unroll
    for (int mf = 0; mf < 2; ++mf)
        #pragma unroll
        for (int h = 0; h < 2; ++h) {
            const int R = wm * 32 + mf * 16 + g + 8 * h;
            rowb[mf * 2 + h] = R * 64 + tig * 4;
            uxr [mf * 2 + h] = (R >> 1) & 3;
        }
    uint32_t bRd[8];
    #pragma unroll
    for (int nf = 0; nf < 8; ++nf) {
        const int n4f = wn * 16 + nf * 2 + (g >> 2);
        bRd[nf] = 8192 + ((n4f ^ (tig << 1)) << 4) + (g & 3) * 4 + tig * 512;
    }

    float acc[2][8][4];
    #pragma unroll
    for (int i = 0; i < 2; ++i)
        #pragma unroll
        for (int j = 0; j < 8; ++j)
            #pragma unroll
            for (int r = 0; r < 4; ++r) acc[i][j][r] = 0.0f;

    auto issue = [&](int kt, int s) {
        const uint32_t sb = smu + s * STAGE;
        const size_t astep = (size_t)kt * 64;               // 16 floats
        const size_t bstep = (size_t)kt * 16 * NTOT * 4;    // 16 k-rows
        #pragma unroll
        for (int j = 0; j < 2; ++j) cp16(sb + aCpOff[j], aCpPtr[j] + astep);
        #pragma unroll
        for (int j = 0; j < 2; ++j) cp16(sb + bCpOff[j], bCpPtr[j] + bstep);
    };

    // ---- prologue: 2 chunks in flight ----
    issue(0, 0);
    asm volatile("cp.async.commit_group;" ::: "memory");
    issue(1, 1);
    asm volatile("cp.async.commit_group;" ::: "memory");

    #pragma unroll 1
    for (int kt = 0; kt < KT; ++kt) {
        asm volatile("cp.async.wait_group 1;" ::: "memory");
        __syncthreads();
        if (kt + 2 < KT) issue(kt + 2, (kt + 2) % 3);
        asm volatile("cp.async.commit_group;" ::: "memory");

        const uint32_t base = smu + (kt % 3) * STAGE;
        #pragma unroll
        for (int ks = 0; ks < 2; ++ks) {
            uint32_t A0[2][4];
            #pragma unroll
            for (int mf = 0; mf < 2; ++mf) {
                float f0, f1, f2, f3;
                asm volatile("ld.shared.f32 %0, [%1];" : "=f"(f0)
                             : "r"(base + rowb[mf*2]   + (((2u*ks)     ^ uxr[mf*2])   << 4)));
                asm volatile("ld.shared.f32 %0, [%1];" : "=f"(f1)
                             : "r"(base + rowb[mf*2+1] + (((2u*ks)     ^ uxr[mf*2+1]) << 4)));
                asm volatile("ld.shared.f32 %0, [%1];" : "=f"(f2)
                             : "r"(base + rowb[mf*2]   + (((2u*ks + 1) ^ uxr[mf*2])   << 4)));
                asm volatile("ld.shared.f32 %0, [%1];" : "=f"(f3)
                             : "r"(base + rowb[mf*2+1] + (((2u*ks + 1) ^ uxr[mf*2+1]) << 4)));
                A0[mf][0] = f2tf(f0); A0[mf][1] = f2tf(f1);
                A0[mf][2] = f2tf(f2); A0[mf][3] = f2tf(f3);
            }
            #pragma unroll
            for (int nf = 0; nf < 8; ++nf) {
                float fb0, fb1;
                asm volatile("ld.shared.f32 %0, [%1];" : "=f"(fb0)
                             : "r"(base + bRd[nf] + ks * 4096u));
                asm volatile("ld.shared.f32 %0, [%1];" : "=f"(fb1)
                             : "r"(base + bRd[nf] + ks * 4096u + 2048u));
                uint32_t B0[2] = { f2tf(fb0), f2tf(fb1) };
                mma8(acc[0][nf], A0[0], B0);
                mma8(acc[1][nf], A0[1], B0);
            }
        }
    }
    __syncthreads();

    // ---- epilogue: two passes of 64 rows through smem staging [64][132] ----
    float* stg = (float*)sm;
    #pragma unroll 1
    for (int pass = 0; pass < 2; ++pass) {
        if ((wm >> 1) == pass) {
            #pragma unroll
            for (int mf = 0; mf < 2; ++mf)
                #pragma unroll
                for (int nf = 0; nf < 8; ++nf) {
                    const int rl  = (wm & 1) * 32 + mf * 16 + g;
                    const int col = wn * 64 + nf * 8 + 2 * tig;
                    *(float2*)&stg[rl * 132 + col] =
                        make_float2(acc[mf][nf][0], acc[mf][nf][1]);
                    *(float2*)&stg[(rl + 8) * 132 + col] =
                        make_float2(acc[mf][nf][2], acc[mf][nf][3]);
                }
        }
        __syncthreads();
        {
            const int rl = tid >> 2;        // 0..63
            const int q  = tid & 3;         // 32-float quarter
            const int rm = m0 + pass * 64 + rl;
            if (rm < cnt) {
                float* dst;
                if (FIRST) dst = g_h + (size_t)(off + rm) * DFF + n0 + q * 32;
                else       dst = Y   + (size_t)g_tok[off + rm] * DOUT + n0 + q * 32;
                const float* bsrc = bias + (size_t)e * NTOT + n0 + q * 32;
                const float* s    = stg + rl * 132 + q * 32;
                #pragma unroll
                for (int j = 0; j < 8; ++j) {
                    float4 v  = *(const float4*)(s + 4 * j);
                    float4 bb = *(const float4*)(bsrc + 4 * j);
                    v.x += bb.x; v.y += bb.y; v.z += bb.z; v.w += bb.w;
                    if (FIRST) {
                        v.x = fmaxf(v.x, 0.f); v.y = fmaxf(v.y, 0.f);
                        v.z = fmaxf(v.z, 0.f); v.w = fmaxf(v.w, 0.f);
                    }
                    *(float4*)(dst + 4 * j) = v;
                }
            }
        }
        __syncthreads();
    }
}

// ===========================================================================
// kernel_launch: NO cudaFuncSetAttribute (dynamic smem <= 48KB default cap).
// ===========================================================================
extern "C" void kernel_launch(void* const* d_in, const int* in_sizes, int n_in,
                              void* d_out, int out_size)
{
    const float* x      = (const float*)d_in[0];
    const int*   groups = (const int*)  d_in[1];
    const float* W1     = (const float*)d_in[2];
    const float* b1     = (const float*)d_in[3];
    const float* W2     = (const float*)d_in[4];
    const float* b2     = (const float*)d_in[5];
    float*       out    = (float*)d_out;

    constexpr int SMEM_DYN = 3 * 16384;   // 49152 = 48KB cap exactly

    route_kernel<<<1, 512>>>(groups);
    moe_mma_gemm<DIN, DFF, true ><<<dim3(DFF / 128, BTOK / 128, NSUB), 256, SMEM_DYN>>>(
        x, W1, b1, nullptr);
    moe_mma_gemm<DFF, DOUT, false><<<dim3(DOUT / 128, BTOK / 128, NSUB), 256, SMEM_DYN>>>(
        nullptr, W2, b2, out);
}

// round 9
// speedup vs baseline: 1.3859x; 1.3859x over previous
#include <cuda_runtime.h>
#include <cstdint>

#define NSUB 8
#define BTOK 4096
#define DIN  512
#define DFF  2048
#define DOUT 512
#define MAXT 40          // max live m-tiles: sum ceil(cnt_e/128) <= 32+7 = 39

// ---- device-global scratch ----
__device__ int   g_tok[BTOK];
__device__ int   g_off[NSUB + 1];
__device__ int   g_tile_e[MAXT];            // expert per live m-tile (-1 = dead)
__device__ int   g_tile_m[MAXT];            // local m0 per live m-tile
__device__ float g_x[(size_t)BTOK * DIN];   // compact, tf32-rounded x
__device__ float g_h[(size_t)BTOK * DFF];   // intermediate h (tf32-rounded)

// ===========================================================================
// Routing + tile table
// ===========================================================================
__global__ void route_kernel(const int* __restrict__ groups)
{
    __shared__ int s_cnt[NSUB];
    __shared__ int s_cur[NSUB];
    const int tid = threadIdx.x;
    if (tid < NSUB) s_cnt[tid] = 0;
    __syncthreads();
    for (int b = tid; b < BTOK; b += blockDim.x)
        atomicAdd(&s_cnt[groups[2 * b]], 1);
    __syncthreads();
    if (tid == 0) {
        int off = 0, t = 0;
        for (int e = 0; e < NSUB; ++e) {
            g_off[e] = off; s_cur[e] = off;
            for (int m0 = 0; m0 < s_cnt[e]; m0 += 128) {
                g_tile_e[t] = e; g_tile_m[t] = m0; ++t;
            }
            off += s_cnt[e];
        }
        g_off[NSUB] = off;
        for (; t < MAXT; ++t) { g_tile_e[t] = -1; g_tile_m[t] = 0; }
    }
    __syncthreads();
    for (int b = tid; b < BTOK; b += blockDim.x) {
        int e = groups[2 * b];
        int pos = atomicAdd(&s_cur[e], 1);
        g_tok[pos] = b;
    }
}

// ===========================================================================
// helpers
// ===========================================================================
__device__ __forceinline__ uint32_t f2tf(float x) {
    uint32_t u;
    asm("cvt.rna.tf32.f32 %0, %1;" : "=r"(u) : "f"(x));
    return u;
}
__device__ __forceinline__ void mma8(float* c, const uint32_t* a, const uint32_t* b) {
    asm volatile(
        "mma.sync.aligned.m16n8k8.row.col.f32.tf32.tf32.f32 "
        "{%0,%1,%2,%3}, {%4,%5,%6,%7}, {%8,%9}, {%0,%1,%2,%3};"
        : "+f"(c[0]), "+f"(c[1]), "+f"(c[2]), "+f"(c[3])
        : "r"(a[0]), "r"(a[1]), "r"(a[2]), "r"(a[3]), "r"(b[0]), "r"(b[1]));
}
__device__ __forceinline__ void cp16(uint32_t dst_smem, const void* src) {
    asm volatile("cp.async.cg.shared.global [%0], [%1], 16;"
                 :: "r"(dst_smem), "l"(src));
}
__device__ __forceinline__ uint32_t smem_u32(const void* p) {
    uint32_t a;
    asm("{ .reg .u64 t; cvta.to.shared.u64 t, %1; cvt.u32.u64 %0, t; }" : "=r"(a) : "l"(p));
    return a;
}

// ===========================================================================
// Gather + tf32-round x into compact token order.
// ===========================================================================
__global__ void gather_x(const float* __restrict__ x)
{
    const int r   = blockIdx.x;
    const int tok = g_tok[r];
    float4 v = *(((const float4*)(x + (size_t)tok * DIN)) + threadIdx.x);
    v.x = __uint_as_float(f2tf(v.x));
    v.y = __uint_as_float(f2tf(v.y));
    v.z = __uint_as_float(f2tf(v.z));
    v.w = __uint_as_float(f2tf(v.w));
    *(((float4*)(g_x + (size_t)r * DIN)) + threadIdx.x) = v;
}

// ===========================================================================
// tf32 mma.sync GEMM: 128x128 tile, BK=16, 3-stage cp.async pipeline,
// tile-table scheduling. A pre-rounded (no cvt); B converted at read.
// ===========================================================================
template <int K, int NTOT, bool FIRST>
__global__ __launch_bounds__(256)
void moe_mma_gemm(const float* __restrict__ W,
                  const float* __restrict__ bias,
                  float* __restrict__ Y)
{
    constexpr int KT    = K / 16;
    constexpr int STAGE = 16384;           // 8KB A + 8KB B

    const int e = g_tile_e[blockIdx.y];
    if (e < 0) return;
    const int m0  = g_tile_m[blockIdx.y];
    const int off = g_off[e];
    const int cnt = g_off[e + 1] - off;
    const int n0  = blockIdx.x * 128;

    const float* A = FIRST ? g_x : g_h;

    extern __shared__ char sm[];
    const uint32_t smu = smem_u32(sm);

    const int tid = threadIdx.x;
    const int wid = tid >> 5, l = tid & 31;
    const int g = l >> 2, tig = l & 3;
    const int wm = wid & 3;
    const int wn = wid >> 2;

    // ---- cp.async mappings ----
    const char* aCpPtr[2];
    uint32_t    aCpOff[2];
    #pragma unroll
    for (int j = 0; j < 2; ++j) {
        const int row = (tid >> 2) + 64 * j;
        const int c4  = tid & 3;
        const int r   = m0 + row;
        const int rr  = (r < cnt) ? r : (cnt - 1);
        aCpPtr[j] = (const char*)(A + (size_t)(off + rr) * K) + c4 * 16;
        aCpOff[j] = row * 64 + ((c4 ^ ((row >> 1) & 3)) << 4);
    }
    const char* bCpPtr[2];
    uint32_t    bCpOff[2];
    #pragma unroll
    for (int j = 0; j < 2; ++j) {
        const int lr = (tid >> 5) + 8 * j;
        const int n4 = tid & 31;
        bCpPtr[j] = (const char*)(W + (size_t)e * K * NTOT + (size_t)lr * NTOT + n0 + n4 * 4);
        bCpOff[j] = 8192 + lr * 512 + ((n4 ^ ((lr & 3) << 1)) << 4);
    }

    // ---- fragment-read bases ----
    uint32_t rowb[4], uxr[4];
    #pragma unroll
    for (int mf = 0; mf < 2; ++mf)
        #pragma unroll
        for (int h = 0; h < 2; ++h) {
            const int R = wm * 32 + mf * 16 + g + 8 * h;
            rowb[mf * 2 + h] = R * 64 + tig * 4;
            uxr [mf * 2 + h] = (R >> 1) & 3;
        }
    uint32_t bRd[8];
    #pragma unroll
    for (int nf = 0; nf < 8; ++nf) {
        const int n4f = wn * 16 + nf * 2 + (g >> 2);
        bRd[nf] = 8192 + ((n4f ^ (tig << 1)) << 4) + (g & 3) * 4 + tig * 512;
    }

    float acc[2][8][4];
    #pragma unroll
    for (int i = 0; i < 2; ++i)
        #pragma unroll
        for (int j = 0; j < 8; ++j)
            #pragma unroll
            for (int r = 0; r < 4; ++r) acc[i][j][r] = 0.0f;

    auto issue = [&](int kt, int s) {
        const uint32_t sb = smu + s * STAGE;
        const size_t astep = (size_t)kt * 64;
        const size_t bstep = (size_t)kt * 16 * NTOT * 4;
        #pragma unroll
        for (int j = 0; j < 2; ++j) cp16(sb + aCpOff[j], aCpPtr[j] + astep);
        #pragma unroll
        for (int j = 0; j < 2; ++j) cp16(sb + bCpOff[j], bCpPtr[j] + bstep);
    };

    issue(0, 0);
    asm volatile("cp.async.commit_group;" ::: "memory");
    issue(1, 1);
    asm volatile("cp.async.commit_group;" ::: "memory");

    #pragma unroll 1
    for (int kt = 0; kt < KT; ++kt) {
        asm volatile("cp.async.wait_group 1;" ::: "memory");
        __syncthreads();
        if (kt + 2 < KT) issue(kt + 2, (kt + 2) % 3);
        asm volatile("cp.async.commit_group;" ::: "memory");

        const char* base = sm + (kt % 3) * STAGE;
        #pragma unroll
        for (int ks = 0; ks < 2; ++ks) {
            uint32_t A0[2][4];
            #pragma unroll
            for (int mf = 0; mf < 2; ++mf) {
                const char* rb0 = base + rowb[mf * 2];
                const char* rb1 = base + rowb[mf * 2 + 1];
                A0[mf][0] = *(const uint32_t*)(rb0 + (((2u * ks)     ^ uxr[mf * 2])     << 4));
                A0[mf][1] = *(const uint32_t*)(rb1 + (((2u * ks)     ^ uxr[mf * 2 + 1]) << 4));
                A0[mf][2] = *(const uint32_t*)(rb0 + (((2u * ks + 1) ^ uxr[mf * 2])     << 4));
                A0[mf][3] = *(const uint32_t*)(rb1 + (((2u * ks + 1) ^ uxr[mf * 2 + 1]) << 4));
            }
            #pragma unroll
            for (int nf = 0; nf < 8; ++nf) {
                const float fb0 = *(const float*)(base + bRd[nf] + ks * 4096u);
                const float fb1 = *(const float*)(base + bRd[nf] + ks * 4096u + 2048u);
                uint32_t B0[2] = { f2tf(fb0), f2tf(fb1) };
                mma8(acc[0][nf], A0[0], B0);
                mma8(acc[1][nf], A0[1], B0);
            }
        }
    }
    __syncthreads();

    // ---- epilogue ----
    float* stg = (float*)sm;
    #pragma unroll 1
    for (int pass = 0; pass < 2; ++pass) {
        if ((wm >> 1) == pass) {
            #pragma unroll
            for (int mf = 0; mf < 2; ++mf)
                #pragma unroll
                for (int nf = 0; nf < 8; ++nf) {
                    const int rl  = (wm & 1) * 32 + mf * 16 + g;
                    const int col = wn * 64 + nf * 8 + 2 * tig;
                    *(float2*)&stg[rl * 132 + col] =
                        make_float2(acc[mf][nf][0], acc[mf][nf][1]);
                    *(float2*)&stg[(rl + 8) * 132 + col] =
                        make_float2(acc[mf][nf][2], acc[mf][nf][3]);
                }
        }
        __syncthreads();
        {
            const int rl = tid >> 2;
            const int q  = tid & 3;
            const int rm = m0 + pass * 64 + rl;
            if (rm < cnt) {
                float* dst;
                if (FIRST) dst = g_h + (size_t)(off + rm) * DFF + n0 + q * 32;
                else       dst = Y   + (size_t)g_tok[off + rm] * DOUT + n0 + q * 32;
                const float* bsrc = bias + (size_t)e * NTOT + n0 + q * 32;
                const float* s    = stg + rl * 132 + q * 32;
                #pragma unroll
                for (int j = 0; j < 8; ++j) {
                    float4 v  = *(const float4*)(s + 4 * j);
                    float4 bb = *(const float4*)(bsrc + 4 * j);
                    v.x += bb.x; v.y += bb.y; v.z += bb.z; v.w += bb.w;
                    if (FIRST) {
                        v.x = __uint_as_float(f2tf(fmaxf(v.x, 0.f)));
                        v.y = __uint_as_float(f2tf(fmaxf(v.y, 0.f)));
                        v.z = __uint_as_float(f2tf(fmaxf(v.z, 0.f)));
                        v.w = __uint_as_float(f2tf(fmaxf(v.w, 0.f)));
                    }
                    *(float4*)(dst + 4 * j) = v;
                }
            }
        }
        __syncthreads();
    }
}

// ===========================================================================
extern "C" void kernel_launch(void* const* d_in, const int* in_sizes, int n_in,
                              void* d_out, int out_size)
{
    const float* x      = (const float*)d_in[0];
    const int*   groups = (const int*)  d_in[1];
    const float* W1     = (const float*)d_in[2];
    const float* b1     = (const float*)d_in[3];
    const float* W2     = (const float*)d_in[4];
    const float* b2     = (const float*)d_in[5];
    float*       out    = (float*)d_out;

    constexpr int SMEM_DYN = 3 * 16384;   // 49152 = 48KB cap exactly

    route_kernel<<<1, 512>>>(groups);
    gather_x<<<BTOK, DIN / 4>>>(x);
    moe_mma_gemm<DIN, DFF, true ><<<dim3(DFF / 128, MAXT), 256, SMEM_DYN>>>(W1, b1, nullptr);
    moe_mma_gemm<DFF, DOUT, false><<<dim3(DOUT / 128, MAXT), 256, SMEM_DYN>>>(W2, b2, out);
}